// round 5
// baseline (speedup 1.0000x reference)
#include <cuda_runtime.h>
#include <cuda_fp16.h>

#define Bx     2
#define Hx     512
#define Wx     1024
#define HWx    (Hx * Wx)          // 524288
#define NSEG   16
#define NBINS  32768
#define BIN_SCALE 16384.0f
#define MINPIX 128.0f
#define BPB    256                // blocks per batch for the big passes

// ---- globals ----
__device__ __align__(16) unsigned long long g_hist[NSEG * NBINS]; // low=neg, high=pos
__device__ __align__(16) float g_acc[NSEG * 6];   // cnt, Se0, Se1, Ss0, Ss1, Q
__device__ __align__(16) float g_seed_bg[Bx];
__device__ __align__(16) float g_fg_s[NSEG];
__device__ __align__(16) float g_lov[NSEG];
__device__ __align__(16) float g_params[NSEG * 4]; // c0 c1 sx0 sx1
// scratch (not zeroed)
__device__ __align__(16) __half g_seeds[Bx * 8 * HWx];       // [b][c][hw]
__device__ __align__(16) unsigned g_mbits[Bx * HWx / 4];     // byte j: bit n = mask n

__device__ const float FGW[8] = {10.0f, 10.0f, 10.0f, 40.0f, 80.0f, 100.0f, 60.0f, 20.0f};

__device__ __forceinline__ float wred(float v) {
    v += __shfl_down_sync(0xffffffffu, v, 16);
    v += __shfl_down_sync(0xffffffffu, v, 8);
    v += __shfl_down_sync(0xffffffffu, v, 4);
    v += __shfl_down_sync(0xffffffffu, v, 2);
    v += __shfl_down_sync(0xffffffffu, v, 1);
    return v;
}

__device__ __forceinline__ float sigmoidf_fast(float x) {
    return __fdividef(1.0f, 1.0f + __expf(-x));
}
// fast tanh, deterministic, used identically in k_sums and k_pass3
__device__ __forceinline__ float tanhf_fast(float x) {
    float t = __expf(2.0f * x);
    return __fdividef(t - 1.0f, t + 1.0f);
}

// packed f32x2 helpers (sm_100+)
__device__ __forceinline__ unsigned long long pack2(float lo, float hi) {
    unsigned long long r;
    asm("mov.b64 %0, {%1, %2};" : "=l"(r) : "f"(lo), "f"(hi));
    return r;
}
__device__ __forceinline__ float2 unpack2(unsigned long long v) {
    float2 r;
    asm("mov.b64 {%0, %1}, %2;" : "=f"(r.x), "=f"(r.y) : "l"(v));
    return r;
}
__device__ __forceinline__ void ffma2(unsigned long long& acc,
                                      unsigned long long a, unsigned long long b) {
    asm("fma.rn.f32x2 %0, %1, %2, %3;" : "=l"(acc) : "l"(a), "l"(b), "l"(acc));
}

// ---------------------------------------------------------------- zero
__global__ void k_zero() {
    size_t tid = blockIdx.x * blockDim.x + threadIdx.x;
    size_t stride = (size_t)gridDim.x * blockDim.x;
    float4* p = reinterpret_cast<float4*>(g_hist);
    for (size_t i = tid; i < sizeof(g_hist) / 16; i += stride)
        p[i] = make_float4(0.f, 0.f, 0.f, 0.f);
    if (blockIdx.x == 0 && threadIdx.x < 160) {
        int t = threadIdx.x;
        if (t < NSEG * 6) g_acc[t] = 0.f;
        if (t < Bx) g_seed_bg[t] = 0.f;
        if (t < NSEG) { g_fg_s[t] = 0.f; g_lov[t] = 0.f; }
    }
}

// ---------------------------------------------------------------- k_sums: masks + ch0-3
__global__ void __launch_bounds__(256, 3) k_sums(const float* __restrict__ pred,
                                                 const int* __restrict__ masks) {
    int b = blockIdx.x / BPB;
    int blk = blockIdx.x % BPB;
    const float* pb = pred + (size_t)b * 12 * HWx;
    const int* mb  = masks + (size_t)b * 8 * HWx;
    unsigned* mbo = g_mbits + (size_t)b * HWx / 4;

    unsigned long long A[8], S[8], C[8];   // (Σm·e0,Σm·e1), (Σm·σ0,Σm·σ1), (cnt,Σm·q)
#pragma unroll
    for (int n = 0; n < 8; n++) { A[n] = 0ull; S[n] = 0ull; C[n] = 0ull; }

    for (int g = blk * 256 + threadIdx.x; g < HWx / 4; g += BPB * 256) {
        int hw = g * 4;
        int w = hw & (Wx - 1);
        int h = hw >> 10;
        float ybase = (float)h * (1.0f / 1023.0f);

        float4 p0 = *(const float4*)(pb + hw);
        float4 p1 = *(const float4*)(pb + HWx + hw);
        float4 s0v = *(const float4*)(pb + 2 * HWx + hw);
        float4 s1v = *(const float4*)(pb + 3 * HWx + hw);

        unsigned long long pe[4], ps[4], pq[4];
        {
            float e0[4], e1[4];
            e0[0] = tanhf_fast(p0.x) + (float)(w + 0) * (2.0f / 2047.0f);
            e0[1] = tanhf_fast(p0.y) + (float)(w + 1) * (2.0f / 2047.0f);
            e0[2] = tanhf_fast(p0.z) + (float)(w + 2) * (2.0f / 2047.0f);
            e0[3] = tanhf_fast(p0.w) + (float)(w + 3) * (2.0f / 2047.0f);
            e1[0] = tanhf_fast(p1.x) + ybase;
            e1[1] = tanhf_fast(p1.y) + ybase;
            e1[2] = tanhf_fast(p1.z) + ybase;
            e1[3] = tanhf_fast(p1.w) + ybase;
            float sg0[4] = {s0v.x, s0v.y, s0v.z, s0v.w};
            float sg1[4] = {s1v.x, s1v.y, s1v.z, s1v.w};
#pragma unroll
            for (int j = 0; j < 4; j++) {
                pe[j] = pack2(e0[j], e1[j]);
                ps[j] = pack2(sg0[j], sg1[j]);
                pq[j] = pack2(1.0f, fmaf(sg0[j], sg0[j], sg1[j] * sg1[j]));
            }
        }

        unsigned bits = 0;
#pragma unroll
        for (int n = 0; n < 8; n++) {
            int4 mv = *(const int4*)(mb + (size_t)n * HWx + hw);
            float mf[4];
            mf[0] = (mv.x > 0) ? 1.f : 0.f;
            mf[1] = (mv.y > 0) ? 1.f : 0.f;
            mf[2] = (mv.z > 0) ? 1.f : 0.f;
            mf[3] = (mv.w > 0) ? 1.f : 0.f;
#pragma unroll
            for (int j = 0; j < 4; j++) {
                unsigned long long mm = pack2(mf[j], mf[j]);
                ffma2(A[n], pe[j], mm);
                ffma2(S[n], ps[j], mm);
                ffma2(C[n], pq[j], mm);
                if (mf[j] != 0.f) bits |= (1u << (n + j * 8));
            }
        }
        mbo[g] = bits;
    }

#pragma unroll
    for (int n = 0; n < 8; n++) {
        int seg = b * 8 + n;
        float2 a = unpack2(A[n]);
        float2 s = unpack2(S[n]);
        float2 c = unpack2(C[n]);
        float v;
        v = wred(c.x); if ((threadIdx.x & 31) == 0) atomicAdd(&g_acc[seg * 6 + 0], v);
        v = wred(a.x); if ((threadIdx.x & 31) == 0) atomicAdd(&g_acc[seg * 6 + 1], v);
        v = wred(a.y); if ((threadIdx.x & 31) == 0) atomicAdd(&g_acc[seg * 6 + 2], v);
        v = wred(s.x); if ((threadIdx.x & 31) == 0) atomicAdd(&g_acc[seg * 6 + 3], v);
        v = wred(s.y); if ((threadIdx.x & 31) == 0) atomicAdd(&g_acc[seg * 6 + 4], v);
        v = wred(c.y); if ((threadIdx.x & 31) == 0) atomicAdd(&g_acc[seg * 6 + 5], v);
    }
}

// ---------------------------------------------------------------- k_seed: ch4-11 + bbox
__global__ void __launch_bounds__(256, 4) k_seed(const float* __restrict__ pred,
                                                 const int* __restrict__ bbox) {
    int b = blockIdx.x / BPB;
    int blk = blockIdx.x % BPB;
    const float* pb = pred + (size_t)b * 12 * HWx;
    const int* bbb = bbox + (size_t)b * 9 * HWx;
    __half* sdo = g_seeds + (size_t)b * 8 * HWx;

    float bg = 0.f;
    for (int g = blk * 256 + threadIdx.x; g < HWx / 4; g += BPB * 256) {
        int hw = g * 4;
#pragma unroll
        for (int c = 0; c < 8; c++) {
            float4 sv = *(const float4*)(pb + (size_t)(4 + c) * HWx + hw);
            int4 bv = *(const int4*)(bbb + (size_t)(1 + c) * HWx + hw);
            float s0 = sigmoidf_fast(sv.x);
            float s1 = sigmoidf_fast(sv.y);
            float s2 = sigmoidf_fast(sv.z);
            float s3 = sigmoidf_fast(sv.w);
            if (bv.x == 0) bg = fmaf(s0, s0, bg);
            if (bv.y == 0) bg = fmaf(s1, s1, bg);
            if (bv.z == 0) bg = fmaf(s2, s2, bg);
            if (bv.w == 0) bg = fmaf(s3, s3, bg);
            __half2 h01 = __floats2half2_rn(s0, s1);
            __half2 h23 = __floats2half2_rn(s2, s3);
            uint2 pk;
            pk.x = *reinterpret_cast<unsigned*>(&h01);
            pk.y = *reinterpret_cast<unsigned*>(&h23);
            *(uint2*)(sdo + (size_t)c * HWx + hw) = pk;
        }
    }
    bg = wred(bg);
    if ((threadIdx.x & 31) == 0) atomicAdd(&g_seed_bg[b], bg);
}

// ---------------------------------------------------------------- params
__global__ void k_params() {
    int t = threadIdx.x;
    if (t < NSEG) {
        float cnt = g_acc[t * 6 + 0];
        float cs = fmaxf(cnt, 1.f);
        float inv = 1.f / cs;
        g_params[t * 4 + 0] = g_acc[t * 6 + 1] * inv;
        g_params[t * 4 + 1] = g_acc[t * 6 + 2] * inv;
        g_params[t * 4 + 2] = expf(g_acc[t * 6 + 3] * inv * 10.f);
        g_params[t * 4 + 3] = expf(g_acc[t * 6 + 4] * inv * 10.f);
    }
}

// ---------------------------------------------------------------- pass3: dist, hist, seed_fg
__global__ void __launch_bounds__(256, 3) k_pass3(const float* __restrict__ pred,
                                                  const int* __restrict__ cls_ids) {
    int b = blockIdx.x / BPB;
    int blk = blockIdx.x % BPB;

    __shared__ float sp[8][4];
    __shared__ int sch[8];
    if (threadIdx.x < 32) {
        int n = threadIdx.x / 4, k = threadIdx.x % 4;
        sp[n][k] = g_params[(b * 8 + n) * 4 + k];
    }
    if (threadIdx.x < 8) sch[threadIdx.x] = cls_ids[b * 8 + threadIdx.x];
    __syncthreads();

    float c0[8], c1[8], sx0[8], sx1[8];
    const __half* sdp[8];
#pragma unroll
    for (int n = 0; n < 8; n++) {
        c0[n] = sp[n][0]; c1[n] = sp[n][1];
        sx0[n] = sp[n][2]; sx1[n] = sp[n][3];
        sdp[n] = g_seeds + ((size_t)b * 8 + sch[n]) * HWx;
    }
    float fa[8] = {0,0,0,0,0,0,0,0};

    const float* pb = pred + (size_t)b * 12 * HWx;
    const unsigned* mbi = g_mbits + (size_t)b * HWx / 4;
    unsigned long long* hb = &g_hist[(size_t)(b * 8) * NBINS];

    for (int g = blk * 256 + threadIdx.x; g < HWx / 4; g += BPB * 256) {
        int hw = g * 4;
        int w = hw & (Wx - 1);
        int h = hw >> 10;
        float ybase = (float)h * (1.0f / 1023.0f);
        float4 p0 = *(const float4*)(pb + hw);
        float4 p1 = *(const float4*)(pb + HWx + hw);
        float e0[4], e1[4];
        e0[0] = tanhf_fast(p0.x) + (float)(w + 0) * (2.0f / 2047.0f);
        e0[1] = tanhf_fast(p0.y) + (float)(w + 1) * (2.0f / 2047.0f);
        e0[2] = tanhf_fast(p0.z) + (float)(w + 2) * (2.0f / 2047.0f);
        e0[3] = tanhf_fast(p0.w) + (float)(w + 3) * (2.0f / 2047.0f);
        e1[0] = tanhf_fast(p1.x) + ybase;
        e1[1] = tanhf_fast(p1.y) + ybase;
        e1[2] = tanhf_fast(p1.z) + ybase;
        e1[3] = tanhf_fast(p1.w) + ybase;
        unsigned bits = mbi[g];

#pragma unroll
        for (int n = 0; n < 8; n++) {
            uint2 svp = *(const uint2*)(sdp[n] + hw);
            __half2 hA = *reinterpret_cast<__half2*>(&svp.x);
            __half2 hB = *reinterpret_cast<__half2*>(&svp.y);
            float2 fA = __half22float2(hA);
            float2 fB = __half22float2(hB);
            float sv[4] = {fA.x, fA.y, fB.x, fB.y};
#pragma unroll
            for (int j = 0; j < 4; j++) {
                int lab = (bits >> (n + j * 8)) & 1;
                float labf = (float)lab;
                float dx = e0[j] - c0[n];
                float dy = e1[j] - c1[n];
                float d2 = fmaf(dx * dx, sx0[n], dy * dy * sx1[n]);
                float dist = __expf(-d2);
                // e = lab ? 2(1-dist) : 2*dist  == 2*|dist - lab|
                float eb = fabsf(dist - labf) * (2.0f * BIN_SCALE);
                int bin = min((int)eb, NBINS - 1);
                atomicAdd(&hb[(size_t)n * NBINS + bin],
                          lab ? (1ull << 32) : 1ull);
                float dd = sv[j] - dist;
                if (lab) fa[n] = fmaf(dd, dd, fa[n]);
            }
        }
    }
#pragma unroll
    for (int n = 0; n < 8; n++) {
        float v = wred(fa[n]);
        if ((threadIdx.x & 31) == 0) atomicAdd(&g_fg_s[b * 8 + n], v);
    }
}

// ---------------------------------------------------------------- Lovász scan
__global__ void __launch_bounds__(1024) k_scan() {
    int seg = blockIdx.x;
    int tid = threadIdx.x;
    int warp = tid >> 5, lane = tid & 31;
    __shared__ unsigned long long wsum[32];
    __shared__ float rs[32];

    double Pd = (double)g_acc[seg * 6 + 0];
    unsigned carry_p = 0, carry_n = 0;
    double lov = 0.0;
    const unsigned long long* hp = &g_hist[(size_t)seg * NBINS];

    for (int it = 0; it < NBINS / 1024; it++) {
        int bin = NBINS - 1 - (it * 1024 + tid);
        unsigned long long pair = hp[bin];
        unsigned nn = (unsigned)(pair & 0xffffffffu);
        unsigned np = (unsigned)(pair >> 32);
        unsigned long long inc = pair;
#pragma unroll
        for (int o = 1; o < 32; o <<= 1) {
            unsigned long long t = __shfl_up_sync(0xffffffffu, inc, o);
            if (lane >= o) inc += t;
        }
        if (lane == 31) wsum[warp] = inc;
        __syncthreads();
        if (warp == 0) {
            unsigned long long wv = wsum[lane];
#pragma unroll
            for (int o = 1; o < 32; o <<= 1) {
                unsigned long long t = __shfl_up_sync(0xffffffffu, wv, o);
                if (lane >= o) wv += t;
            }
            wsum[lane] = wv;
        }
        __syncthreads();
        unsigned long long incl = inc + (warp > 0 ? wsum[warp - 1] : 0ull);
        unsigned long long total = wsum[31];
        unsigned cp1 = carry_p + (unsigned)(incl >> 32);
        unsigned cn1 = carry_n + (unsigned)(incl & 0xffffffffu);
        unsigned cp0 = cp1 - np;
        unsigned cn0 = cn1 - nn;
        if (np | nn) {
            double j1 = 1.0 - (Pd - (double)cp1) / fmax(Pd + (double)cn1, 1.0);
            double j0 = 1.0 - (Pd - (double)cp0) / fmax(Pd + (double)cn0, 1.0);
            lov += ((double)bin + 0.5) * (1.0 / 16384.0) * (j1 - j0);
        }
        carry_p += (unsigned)(total >> 32);
        carry_n += (unsigned)(total & 0xffffffffu);
        __syncthreads();
    }
    float lf = wred((float)lov);
    if (lane == 0) rs[warp] = lf;
    __syncthreads();
    if (tid < 32) {
        float v = wred(rs[tid]);
        if (tid == 0) g_lov[seg] = v;
    }
}

// ---------------------------------------------------------------- final
__global__ void k_final(const int* __restrict__ cls_ids, float* __restrict__ out) {
    if (threadIdx.x == 0 && blockIdx.x == 0) {
        float total = 0.f;
        for (int b = 0; b < Bx; b++) {
            float obj = 0.f, inst = 0.f, var = 0.f, fg = 0.f;
            for (int n = 0; n < 8; n++) {
                int seg = b * 8 + n;
                float cnt = g_acc[seg * 6 + 0];
                float valid = (cnt >= MINPIX) ? 1.f : 0.f;
                float cs = fmaxf(cnt, 1.f);
                float S0 = g_acc[seg * 6 + 3];
                float S1 = g_acc[seg * 6 + 4];
                float Q  = g_acc[seg * 6 + 5];
                float vi = (Q - (S0 * S0 + S1 * S1) / cs) / (2.f * cs);
                obj += valid;
                inst += g_lov[seg] * valid;
                var += vi * valid;
                fg += FGW[cls_ids[seg]] * g_fg_s[seg] * valid;
            }
            float os = fmaxf(obj, 1.f);
            float seed_l = (g_seed_bg[b] + fg) * (1.0f / (float)HWx);
            total += inst / os + 10.f * (var / os) + seed_l;
        }
        out[0] = total * 0.5f;
    }
}

// ---------------------------------------------------------------- launch
extern "C" void kernel_launch(void* const* d_in, const int* in_sizes, int n_in,
                              void* d_out, int out_size) {
    const float* pred = (const float*)d_in[0];
    const int* bbox   = (const int*)d_in[1];
    const int* masks  = (const int*)d_in[2];
    const int* cls    = (const int*)d_in[3];
    (void)in_sizes; (void)n_in; (void)out_size;

    k_zero<<<512, 256>>>();
    k_sums<<<Bx * BPB, 256>>>(pred, masks);
    k_seed<<<Bx * BPB, 256>>>(pred, bbox);
    k_params<<<1, 32>>>();
    k_pass3<<<Bx * BPB, 256>>>(pred, cls);
    k_scan<<<NSEG, 1024>>>();
    k_final<<<1, 32>>>(cls, (float*)d_out);
}